// round 17
// baseline (speedup 1.0000x reference)
#include <cuda_runtime.h>
#include <cuda_fp16.h>
#include <math.h>
#include <stdint.h>

#define BATCH 4
#define CH 256
#define NSP 4096            // h*w
#define GROUPS 8
#define GELEMS (32*NSP)     // elems per (b,group)
#define EPS 1e-5f

// ---------------- scratch (device globals) ----------------
__device__ __half g_xnt [BATCH*NSP*CH];          // groupnorm out fp16 [b][p][c]
__device__ __half g_qkvt[BATCH*NSP*2*CH];        // Q,K fp16 [b][p][512]
__device__ __half g_vt  [BATCH*CH*NSP];          // V^T fp16 [b][c][p]
__device__ __half g_attn[BATCH*NSP*CH];          // attention out fp16 [b][p][c]
__device__ __half g_wq  [3*CH*CH];               // w_qkv fp16
__device__ __half g_wp  [CH*CH];                 // w_proj fp16
__device__ float  g_gnpart[BATCH*GROUPS*8*2];

// ---------------- GroupNorm partial reduction ----------------
__global__ void gn_partial(const float* __restrict__ x) {
    int blk = blockIdx.x;
    int bg = blk >> 3, slice = blk & 7;
    const float4* p4 = (const float4*)(x + bg*GELEMS + slice*(GELEMS/8));
    float s = 0.f, sq = 0.f;
    for (int i = threadIdx.x; i < GELEMS/8/4; i += 256) {
        float4 v = p4[i];
        s  += v.x + v.y + v.z + v.w;
        sq += v.x*v.x + v.y*v.y + v.z*v.z + v.w*v.w;
    }
    __shared__ float ss[256], ssq[256];
    ss[threadIdx.x] = s; ssq[threadIdx.x] = sq;
    __syncthreads();
    for (int st = 128; st > 0; st >>= 1) {
        if (threadIdx.x < st) {
            ss[threadIdx.x]  += ss[threadIdx.x + st];
            ssq[threadIdx.x] += ssq[threadIdx.x + st];
        }
        __syncthreads();
    }
    if (threadIdx.x == 0) {
        g_gnpart[blk*2 + 0] = ss[0];
        g_gnpart[blk*2 + 1] = ssq[0];
    }
}

// ---------------- GroupNorm apply + transpose -> fp16 [b][p][c] ----------------
__global__ __launch_bounds__(256) void gn_apply_t(const float* __restrict__ x,
                                                  const float* __restrict__ gamma,
                                                  const float* __restrict__ beta) {
    __shared__ float tile[64][65];
    __shared__ float s_ga[64], s_be[64];
    int b = blockIdx.z;
    int p0 = blockIdx.x*64, c0 = blockIdx.y*64;
    int t = threadIdx.x;
    if (t < 64) {
        int c = c0 + t;
        int bg = b*GROUPS + (c >> 5);
        float s = 0.f, sq = 0.f;
#pragma unroll
        for (int k = 0; k < 8; k++) { s += g_gnpart[(bg*8+k)*2]; sq += g_gnpart[(bg*8+k)*2+1]; }
        float mean = s * (1.f/GELEMS);
        float var  = sq * (1.f/GELEMS) - mean*mean;
        float rstd = rsqrtf(var + EPS);
        float ga = gamma[c]*rstd;
        s_ga[t] = ga; s_be[t] = beta[c] - mean*ga;
    }
    __syncthreads();
    const float* X = x + (size_t)b*CH*NSP;
    int cr = t >> 4, p4 = (t & 15)*4;
#pragma unroll
    for (int i = 0; i < 4; i++) {
        int c = cr + i*16;
        float4 v = *(const float4*)&X[(size_t)(c0+c)*NSP + p0 + p4];
        float ga = s_ga[c], be = s_be[c];
        v.x = v.x*ga + be; v.y = v.y*ga + be; v.z = v.z*ga + be; v.w = v.w*ga + be;
        tile[c][p4+0] = v.x; tile[c][p4+1] = v.y; tile[c][p4+2] = v.z; tile[c][p4+3] = v.w;
    }
    __syncthreads();
    __half* O = g_xnt + (size_t)b*NSP*CH;
    int pr = t >> 4, c4 = (t & 15)*4;
#pragma unroll
    for (int i = 0; i < 4; i++) {
        int p = pr + i*16;
        __half2 lo = __floats2half2_rn(tile[c4+0][p], tile[c4+1][p]);
        __half2 hi = __floats2half2_rn(tile[c4+2][p], tile[c4+3][p]);
        uint2 pk; pk.x = *(uint32_t*)&lo; pk.y = *(uint32_t*)&hi;
        *(uint2*)&O[(size_t)(p0+p)*CH + c0 + c4] = pk;
    }
}

// ---------------- fp32 -> fp16 weight conversion (both weights, one launch) ----------------
__global__ void conv_f16_all(const float* __restrict__ wq, const float* __restrict__ wp) {
    int i = (blockIdx.x*256 + threadIdx.x) * 4;
    const float* src; __half* dst; int off;
    if (i < 3*CH*CH) { src = wq; dst = g_wq; off = i; }
    else             { src = wp; dst = g_wp; off = i - 3*CH*CH; }
    float4 v = *(const float4*)&src[off];
    __half2 lo = __floats2half2_rn(v.x, v.y);
    __half2 hi = __floats2half2_rn(v.z, v.w);
    uint2 pk; pk.x = *(uint32_t*)&lo; pk.y = *(uint32_t*)&hi;
    *(uint2*)&dst[off] = pk;
}

#define MMA_F16(d, a, b) \
    asm volatile("mma.sync.aligned.m16n8k16.row.col.f32.f16.f16.f32 " \
        "{%0,%1,%2,%3}, {%4,%5,%6,%7}, {%8,%9}, {%0,%1,%2,%3};" \
        : "+f"((d)[0]), "+f"((d)[1]), "+f"((d)[2]), "+f"((d)[3]) \
        : "r"((a)[0]), "r"((a)[1]), "r"((a)[2]), "r"((a)[3]), \
          "r"((b)[0]), "r"((b)[1]))

#define LDSM_X4(r0, r1, r2, r3, addr) \
    asm volatile("ldmatrix.sync.aligned.m8n8.x4.shared.b16 {%0,%1,%2,%3}, [%4];" \
        : "=r"(r0), "=r"(r1), "=r"(r2), "=r"(r3) : "r"(addr))

#define EX2_H2(dst, src) \
    asm("ex2.approx.f16x2 %0, %1;" : "=r"(dst) : "r"(src))

#define CPA16(so, gp) \
    asm volatile("cp.async.cg.shared.global [%0], [%1], 16;" :: "r"(so), "l"(gp))
#define CPA_COMMIT() asm volatile("cp.async.commit_group;" ::: "memory")
#define CPA_WAIT2()  asm volatile("cp.async.wait_group 2;" ::: "memory")
#define CPA_WAIT3()  asm volatile("cp.async.wait_group 3;" ::: "memory")

// ldmatrix per-lane byte offsets (stride in halfs = STR)
#define AOFF(l, STR) ((((l) & 15)*(STR) + (((l) >> 4) << 3)) * 2)
#define BOFF(l, STR) (((((l) & 7) + (((l) >> 4) << 3))*(STR) + ((((l) >> 3) & 1) << 3)) * 2)

// ================= fused flash attention (512 threads, 16 warps 2x8) =================
// grid (32 q-tiles, 4 batches). Q resident; 32 KV chunks of 128.
// Per chunk: 8 K-tiles (S, warp tile 64x16) + 4 V-tiles (PV, warp tile 64x32).
// 5-slot cp.async ring, depth-4 prefetch. No-max softmax with h2 ex2.
#define FSTR 40
#define QCHH (128*FSTR)
#define PCHH (128*FSTR)
#define RSLOTH (256*FSTR)
#define NRING 5
#define FSMEM ((8*QCHH + 4*PCHH + NRING*RSLOTH)*2 + 512 + 16)

__global__ __launch_bounds__(512, 1) void flash_attn() {
    extern __shared__ __half smh[];
    __half* Qs   = smh;                      // 8 chunks x [128][40]
    __half* Ps   = smh + 8*QCHH;             // 4 chunks x [128][40]
    __half* Ring = Ps + 4*PCHH;              // NRING slots x [256][40]
    float*  sl   = (float*)(Ring + NRING*RSLOTH);

    int t = threadIdx.x;
    int lane = t & 31, wid = t >> 5;
    int g = lane >> 2, tg = lane & 3;
    int wm = wid >> 3, wn = wid & 7;          // 2 x 8
    int p0 = blockIdx.x * 128;
    long b = blockIdx.y;
    const __half* QK = g_qkvt + b*(long)NSP*512;
    const __half* VT = g_vt   + b*(long)CH*NSP;

    int lrow = t >> 2, lc = (t & 3) * 8;      // 128 rows covered by 512 threads
    uint32_t qsu   = (uint32_t)__cvta_generic_to_shared(Qs);
    uint32_t psu   = (uint32_t)__cvta_generic_to_shared(Ps);
    uint32_t ringu = (uint32_t)__cvta_generic_to_shared(Ring);
    uint32_t aoff = AOFF(lane, FSTR);
    uint32_t boff = BOFF(lane, FSTR);

    // ---- resident Q load (8 chunks of 32 k) ----
#pragma unroll
    for (int c = 0; c < 8; c++) {
        uint32_t so = qsu + (c*QCHH + lrow*FSTR + lc)*2;
        const __half* gp = QK + (long)(p0+lrow)*512 + c*32 + lc;
        CPA16(so, gp);
    }
    CPA_COMMIT();
    if (t < 128) sl[t] = 0.f;

    // tile issue: j<8 -> K tile (128 rows); j>=8 -> V tile (256 rows)
    auto issue = [&](int c, int j, int slot) {
        uint32_t sb = ringu + slot*RSLOTH*2;
        int kv0 = c*128;
        if (j < 8) {
            uint32_t so = sb + (lrow*FSTR + lc)*2;
            const __half* gp = QK + (long)(kv0+lrow)*512 + 256 + j*32 + lc;
            CPA16(so, gp);
        } else {
#pragma unroll
            for (int i = 0; i < 2; i++) {
                int row = lrow + i*128;
                uint32_t so = sb + (row*FSTR + lc)*2;
                const __half* gp = VT + (long)row*NSP + kv0 + (j-8)*32 + lc;
                CPA16(so, gp);
            }
        }
    };

    float oacc[4][4][4];
#pragma unroll
    for (int mi = 0; mi < 4; mi++)
#pragma unroll
        for (int nj = 0; nj < 4; nj++)
#pragma unroll
            for (int r = 0; r < 4; r++) oacc[mi][nj][r] = 0.f;
    float sacc[4][2][4];
#pragma unroll
    for (int mi = 0; mi < 4; mi++)
#pragma unroll
        for (int nj = 0; nj < 2; nj++)
#pragma unroll
            for (int r = 0; r < 4; r++) sacc[mi][nj][r] = 0.f;

    const int NCH = NSP/128;       // 32 chunks
    const int T = NCH*12;
    const float ESL = 0.0625f * 1.44269504f;     // scale * log2(e)
    const __half2 hclamp = __float2half2_rn(11.0f);

    // prologue: depth-4 prefetch
    issue(0, 0, 0); CPA_COMMIT();
    issue(0, 1, 1); CPA_COMMIT();
    issue(0, 2, 2); CPA_COMMIT();
    issue(0, 3, 3); CPA_COMMIT();
    int nc = 0, njx = 4;

    for (int gt = 0; gt < T; gt++) {
        int j = gt % 12;
        int slot = gt % NRING;
        CPA_WAIT3();
        __syncthreads();
        if (gt + 4 < T) issue(nc, njx, (gt+4) % NRING);
        CPA_COMMIT();
        if (++njx == 12) { njx = 0; nc++; }

        if (j < 8) {
            // ---- S step: warp tile 64x16 ----
            uint32_t Abase = qsu + (j*QCHH + (wm*64)*FSTR)*2 + aoff;
            uint32_t Bbase = ringu + (slot*RSLOTH + (wn*16)*FSTR)*2 + boff;
#pragma unroll
            for (int kk = 0; kk < 32; kk += 16) {
                uint32_t af[4][4];
#pragma unroll
                for (int mi = 0; mi < 4; mi++)
                    LDSM_X4(af[mi][0], af[mi][1], af[mi][2], af[mi][3],
                            Abase + (mi*16*FSTR + kk)*2);
                uint32_t bfa[2], bfb[2];
                LDSM_X4(bfa[0], bfa[1], bfb[0], bfb[1], Bbase + kk*2);
#pragma unroll
                for (int mi = 0; mi < 4; mi++) {
                    MMA_F16(sacc[mi][0], af[mi], bfa);
                    MMA_F16(sacc[mi][1], af[mi], bfb);
                }
            }
            if (j == 7) {
                // ---- exp (h2 ex2) + P->SMEM + rowsum; reset sacc ----
                // warp wn owns kv-cols [wn*16, wn*16+16) -> chunk wn>>1, offset (wn&1)*16
                __half* Pb = Ps + (wn >> 1)*PCHH;
                int cb0 = (wn & 1)*16;
#pragma unroll
                for (int mi = 0; mi < 4; mi++) {
                    int r0l = wm*64 + mi*16 + g;
                    int r1l = r0l + 8;
                    __half2 rsh0 = __float2half2_rn(0.f);
                    __half2 rsh1 = __float2half2_rn(0.f);
#pragma unroll
                    for (int nj = 0; nj < 2; nj++) {
                        int colb = cb0 + nj*8 + tg*2;
                        float y00 = sacc[mi][nj][0]*ESL, y01 = sacc[mi][nj][1]*ESL;
                        float y10 = sacc[mi][nj][2]*ESL, y11 = sacc[mi][nj][3]*ESL;
                        __half2 h0 = __hmin2(__floats2half2_rn(y00, y01), hclamp);
                        __half2 h1 = __hmin2(__floats2half2_rn(y10, y11), hclamp);
                        uint32_t p0r, p1r;
                        EX2_H2(p0r, *(uint32_t*)&h0);
                        EX2_H2(p1r, *(uint32_t*)&h1);
                        __half2 e0 = *(__half2*)&p0r, e1 = *(__half2*)&p1r;
                        *(__half2*)(Pb + r0l*FSTR + colb) = e0;
                        *(__half2*)(Pb + r1l*FSTR + colb) = e1;
                        rsh0 = __hadd2(rsh0, e0);
                        rsh1 = __hadd2(rsh1, e1);
                        sacc[mi][nj][0] = 0.f; sacc[mi][nj][1] = 0.f;
                        sacc[mi][nj][2] = 0.f; sacc[mi][nj][3] = 0.f;
                    }
                    float rs0 = __low2float(rsh0) + __high2float(rsh0);
                    float rs1 = __low2float(rsh1) + __high2float(rsh1);
                    rs0 += __shfl_xor_sync(~0u, rs0, 1);
                    rs0 += __shfl_xor_sync(~0u, rs0, 2);
                    rs1 += __shfl_xor_sync(~0u, rs1, 1);
                    rs1 += __shfl_xor_sync(~0u, rs1, 2);
                    if (tg == 0) {
                        atomicAdd(&sl[r0l], rs0);
                        atomicAdd(&sl[r1l], rs1);
                    }
                }
            }
        } else {
            // ---- PV step: warp tile 64x32 ----
            int kt = j - 8;
            uint32_t Abase = psu + (kt*PCHH + (wm*64)*FSTR)*2 + aoff;
            uint32_t Bbase = ringu + (slot*RSLOTH + (wn*32)*FSTR)*2 + boff;
#pragma unroll
            for (int kk = 0; kk < 32; kk += 16) {
                uint32_t af[4][4];
#pragma unroll
                for (int mi = 0; mi < 4; mi++)
                    LDSM_X4(af[mi][0], af[mi][1], af[mi][2], af[mi][3],
                            Abase + (mi*16*FSTR + kk)*2);
#pragma unroll
                for (int njp = 0; njp < 2; njp++) {
                    uint32_t bfa[2], bfb[2];
                    LDSM_X4(bfa[0], bfa[1], bfb[0], bfb[1],
                            Bbase + (njp*16*FSTR + kk)*2);
#pragma unroll
                    for (int mi = 0; mi < 4; mi++) {
                        MMA_F16(oacc[mi][njp*2+0], af[mi], bfa);
                        MMA_F16(oacc[mi][njp*2+1], af[mi], bfb);
                    }
                }
            }
        }
    }

    __syncthreads();   // all rowsum atomics done
    __half* O = g_attn + b*(long)NSP*CH;
#pragma unroll
    for (int mi = 0; mi < 4; mi++) {
        int r0l = wm*64 + mi*16 + g;
        int r1l = r0l + 8;
        float inv0 = 1.0f / sl[r0l];
        float inv1 = 1.0f / sl[r1l];
#pragma unroll
        for (int nj = 0; nj < 4; nj++) {
            int ch = wn*32 + nj*8 + tg*2;
            __half2 h0 = __floats2half2_rn(oacc[mi][nj][0]*inv0, oacc[mi][nj][1]*inv0);
            __half2 h1 = __floats2half2_rn(oacc[mi][nj][2]*inv1, oacc[mi][nj][3]*inv1);
            *(__half2*)&O[(long)(p0 + r0l)*CH + ch] = h0;
            *(__half2*)&O[(long)(p0 + r1l)*CH + ch] = h1;
        }
    }
}

// ================= fp16 GEMM (512 threads, 16 warps 2x8) =================
// EPI: 0 = +bias[n], fp16 out   (QK)
//      1 = +bias[m], fp16 out   (V-direct)
//      3 = +bias[m] + res[m][n], fp32 out (proj)
#define BM 128
#define BN 256
#define BK 32
#define BTS 40
#define ATILB (128*BTS)
#define BTILB (256*BTS)
#define NSTG 4
#define SMEMSZ (NSTG*(ATILB+BTILB)*2)    // 122880 B

template<int EPI>
__global__ __launch_bounds__(512, 1) void mm_f16(
    const __half* __restrict__ Ag, int lda, long sAb,
    const __half* __restrict__ Bg, int ldb, long sBb,
    void* __restrict__ Cg, int ldc, long sCb,
    const float* __restrict__ bias,
    const float* __restrict__ resg, long sRb,
    int K)
{
    extern __shared__ __half smh2[];
    __half* As[NSTG] = { smh2, smh2 + ATILB, smh2 + 2*ATILB, smh2 + 3*ATILB };
    __half* Bs[NSTG] = { smh2 + 4*ATILB,             smh2 + 4*ATILB + BTILB,
                         smh2 + 4*ATILB + 2*BTILB,   smh2 + 4*ATILB + 3*BTILB };

    int t = threadIdx.x;
    int wid = t >> 5, lane = t & 31;
    int g = lane >> 2, tg = lane & 3;
    int wm = wid >> 3, wn = wid & 7;          // 2 x 8, warp tile 64x32
    int n0 = blockIdx.x * BN, m0 = blockIdx.y * BM;
    long b = blockIdx.z;
    const __half* A = Ag + b*sAb;
    const __half* B = Bg + b*sBb;
    uint32_t aoff = AOFF(lane, BTS);
    uint32_t boff = BOFF(lane, BTS);

    int lrow = t >> 2, lc = (t & 3) * 8;      // 128 rows per pass
    auto loadAB = [&](int buf, int k0) {
        uint32_t sa = (uint32_t)__cvta_generic_to_shared(As[buf]);
        uint32_t sb = (uint32_t)__cvta_generic_to_shared(Bs[buf]);
        {
            uint32_t so = sa + (lrow*BTS + lc) * 2;
            const __half* gp = A + (long)(m0+lrow)*lda + k0 + lc;
            CPA16(so, gp);
        }
#pragma unroll
        for (int i = 0; i < 2; i++) {
            int row = lrow + i*128;
            uint32_t so = sb + (row*BTS + lc) * 2;
            const __half* gp = B + (long)(n0+row)*ldb + k0 + lc;
            CPA16(so, gp);
        }
    };

    float acc[4][4][4];
#pragma unroll
    for (int mi = 0; mi < 4; mi++)
#pragma unroll
        for (int nj = 0; nj < 4; nj++)
#pragma unroll
            for (int r = 0; r < 4; r++) acc[mi][nj][r] = 0.f;

    const int NK = K / BK;
    loadAB(0, 0);      CPA_COMMIT();
    loadAB(1, BK);     CPA_COMMIT();
    loadAB(2, 2*BK);   CPA_COMMIT();

    int cur = 0;
    for (int kt = 0; kt < NK; kt++) {
        CPA_WAIT2();
        __syncthreads();
        if (kt + 3 < NK) loadAB((kt + 3) % NSTG, (kt+3)*BK);
        CPA_COMMIT();

        uint32_t Abase = (uint32_t)__cvta_generic_to_shared(As[cur]) + ((wm*64)*BTS)*2 + aoff;
        uint32_t Bbase = (uint32_t)__cvta_generic_to_shared(Bs[cur]) + ((wn*32)*BTS)*2 + boff;
#pragma unroll
        for (int kk = 0; kk < BK; kk += 16) {
            uint32_t af[4][4];
#pragma unroll
            for (int mi = 0; mi < 4; mi++)
                LDSM_X4(af[mi][0], af[mi][1], af[mi][2], af[mi][3],
                        Abase + (mi*16*BTS + kk)*2);
#pragma unroll
            for (int njp = 0; njp < 2; njp++) {
                uint32_t bfa[2], bfb[2];
                LDSM_X4(bfa[0], bfa[1], bfb[0], bfb[1],
                        Bbase + (njp*16*BTS + kk)*2);
#pragma unroll
                for (int mi = 0; mi < 4; mi++) {
                    MMA_F16(acc[mi][njp*2+0], af[mi], bfa);
                    MMA_F16(acc[mi][njp*2+1], af[mi], bfb);
                }
            }
        }
        cur = (cur + 1 == NSTG) ? 0 : cur + 1;
    }

    int mb = m0 + wm*64;
    int nb = n0 + wn*32;
    float* Cf = (float*)Cg;
    __half* Ch = (__half*)Cg;
#pragma unroll
    for (int mi = 0; mi < 4; mi++) {
        int r0 = mb + mi*16 + g;
        int r1 = r0 + 8;
        float add0 = 0.f, add1 = 0.f;
        if (EPI == 1 || EPI == 3) { add0 = bias[r0]; add1 = bias[r1]; }
#pragma unroll
        for (int nj = 0; nj < 4; nj++) {
            int col = nb + nj*8 + tg*2;
            float2 v0 = make_float2(acc[mi][nj][0], acc[mi][nj][1]);
            float2 v1 = make_float2(acc[mi][nj][2], acc[mi][nj][3]);
            long o0 = (long)r0*ldc + col + b*sCb;
            long o1 = (long)r1*ldc + col + b*sCb;
            if (EPI == 0) {
                float2 bv = *(const float2*)&bias[col];
                v0.x += bv.x; v0.y += bv.y; v1.x += bv.x; v1.y += bv.y;
                *(__half2*)&Ch[o0] = __floats2half2_rn(v0.x, v0.y);
                *(__half2*)&Ch[o1] = __floats2half2_rn(v1.x, v1.y);
            }
            if (EPI == 1) {
                v0.x += add0; v0.y += add0; v1.x += add1; v1.y += add1;
                *(__half2*)&Ch[o0] = __floats2half2_rn(v0.x, v0.y);
                *(__half2*)&Ch[o1] = __floats2half2_rn(v1.x, v1.y);
            }
            if (EPI == 3) {
                const float* R = resg + b*sRb;
                float2 x0 = *(const float2*)&R[(long)r0*ldc + col];
                float2 x1 = *(const float2*)&R[(long)r1*ldc + col];
                v0.x += add0 + x0.x; v0.y += add0 + x0.y;
                v1.x += add1 + x1.x; v1.y += add1 + x1.y;
                *(float2*)&Cf[o0] = v0;
                *(float2*)&Cf[o1] = v1;
            }
        }
    }
}

// ---------------- launch ----------------
extern "C" void kernel_launch(void* const* d_in, const int* in_sizes, int n_in,
                              void* d_out, int out_size) {
    const float* x      = (const float*)d_in[0];
    const float* gamma  = (const float*)d_in[1];
    const float* beta   = (const float*)d_in[2];
    const float* w_qkv  = (const float*)d_in[3];
    const float* b_qkv  = (const float*)d_in[4];
    const float* w_proj = (const float*)d_in[5];
    const float* b_proj = (const float*)d_in[6];
    float* out = (float*)d_out;

    __half *p_xnt, *p_qkvt, *p_vt, *p_attn, *p_wq, *p_wp;
    cudaGetSymbolAddress((void**)&p_xnt,  g_xnt);
    cudaGetSymbolAddress((void**)&p_qkvt, g_qkvt);
    cudaGetSymbolAddress((void**)&p_vt,   g_vt);
    cudaGetSymbolAddress((void**)&p_attn, g_attn);
    cudaGetSymbolAddress((void**)&p_wq,   g_wq);
    cudaGetSymbolAddress((void**)&p_wp,   g_wp);

    cudaFuncSetAttribute(mm_f16<0>, cudaFuncAttributeMaxDynamicSharedMemorySize, SMEMSZ);
    cudaFuncSetAttribute(mm_f16<1>, cudaFuncAttributeMaxDynamicSharedMemorySize, SMEMSZ);
    cudaFuncSetAttribute(mm_f16<3>, cudaFuncAttributeMaxDynamicSharedMemorySize, SMEMSZ);
    cudaFuncSetAttribute(flash_attn, cudaFuncAttributeMaxDynamicSharedMemorySize, FSMEM);

    // 1-2. GroupNorm (apply fused with transpose, fp16 out)
    gn_partial<<<BATCH*GROUPS*8, 256>>>(x);
    gn_apply_t<<<dim3(NSP/64, CH/64, BATCH), 256>>>(x, gamma, beta);

    // weights -> fp16 (one launch)
    conv_f16_all<<<4*CH*CH/4/256, 256>>>(w_qkv, w_proj);

    // 3. QK: D[p][o] = xnt[p][c] * w_qk[o][c]^T + b[o], o in [0,512)  (fp16 out)
    mm_f16<0><<<dim3(2*CH/BN, NSP/BM, BATCH), 512, SMEMSZ>>>(
        p_xnt, CH, (long)NSP*CH,
        p_wq, CH, 0,
        p_qkvt, 2*CH, (long)NSP*2*CH,
        b_qkv, nullptr, 0, CH);

    // 4. V direct-transposed: Vt[c][p] = w_v[c][:] . xnt[p][:] + b_v[c]  (fp16 out)
    mm_f16<1><<<dim3(NSP/BN, CH/BM, BATCH), 512, SMEMSZ>>>(
        p_wq + 512*CH, CH, 0,
        p_xnt, CH, (long)NSP*CH,
        p_vt, NSP, (long)CH*NSP,
        b_qkv + 512, nullptr, 0, CH);

    // 5. fused attention: S -> exp -> PV, P in SMEM only
    flash_attn<<<dim3(NSP/128, BATCH), 512, FSMEM>>>();

    // 6. out[co][p] = w_proj[co][c] * attn[p][c]^T + b_proj[co] + x   (fp32 out)
    mm_f16<3><<<dim3(NSP/BN, CH/BM, BATCH), 512, SMEMSZ>>>(
        p_wp, CH, 0,
        p_attn, CH, (long)NSP*CH,
        out, NSP, (long)CH*NSP,
        b_proj, x, (long)CH*NSP, CH);
}